// round 2
// baseline (speedup 1.0000x reference)
#include <cuda_runtime.h>

#define NTHREADS 128

// Broadcast one fp32 into a packed f32x2 register pair.
static __device__ __forceinline__ unsigned long long bcast2(float x)
{
    unsigned long long r;
    unsigned u = __float_as_uint(x);
    asm("mov.b64 %0, {%1, %1};" : "=l"(r) : "r"(u));
    return r;
}

// One tap: 4 positions x 32 outputs (16 packed f32x2 each).
// wrow -> w[k][half*32 .. +31] in SMEM (128B aligned). xv[4] = x values.
static __device__ __forceinline__ void tap4(unsigned long long* __restrict__ acc,
                                            const float* __restrict__ wrow,
                                            float xv0, float xv1, float xv2, float xv3)
{
    unsigned long long xx0 = bcast2(xv0), xx1 = bcast2(xv1);
    unsigned long long xx2 = bcast2(xv2), xx3 = bcast2(xv3);
    const ulonglong2* wq = reinterpret_cast<const ulonglong2*>(wrow);
#pragma unroll
    for (int q = 0; q < 8; ++q) {
        ulonglong2 wv = wq[q];
        asm("fma.rn.f32x2 %0, %1, %2, %0;" : "+l"(acc[0 * 16 + 2 * q])     : "l"(xx0), "l"(wv.x));
        asm("fma.rn.f32x2 %0, %1, %2, %0;" : "+l"(acc[0 * 16 + 2 * q + 1]) : "l"(xx0), "l"(wv.y));
        asm("fma.rn.f32x2 %0, %1, %2, %0;" : "+l"(acc[1 * 16 + 2 * q])     : "l"(xx1), "l"(wv.x));
        asm("fma.rn.f32x2 %0, %1, %2, %0;" : "+l"(acc[1 * 16 + 2 * q + 1]) : "l"(xx1), "l"(wv.y));
        asm("fma.rn.f32x2 %0, %1, %2, %0;" : "+l"(acc[2 * 16 + 2 * q])     : "l"(xx2), "l"(wv.x));
        asm("fma.rn.f32x2 %0, %1, %2, %0;" : "+l"(acc[2 * 16 + 2 * q + 1]) : "l"(xx2), "l"(wv.y));
        asm("fma.rn.f32x2 %0, %1, %2, %0;" : "+l"(acc[3 * 16 + 2 * q])     : "l"(xx3), "l"(wv.x));
        asm("fma.rn.f32x2 %0, %1, %2, %0;" : "+l"(acc[3 * 16 + 2 * q + 1]) : "l"(xx3), "l"(wv.y));
    }
}

// ---------------------------------------------------------------------------
// One CTA = one batch, one 16x16 tile of low-res positions.
// 128 threads: half = lane>>4 selects outputs [0,32) or [32,64);
// group g = warp*16 + (lane&15): col j = g&15, rows r0..r0+3 with r0=4*(g>>4).
// ---------------------------------------------------------------------------
__global__ void __launch_bounds__(NTHREADS, 3)
sr_kernel(const float* __restrict__ gx0, const float* __restrict__ gx1,
          const float* __restrict__ gx2, const float* __restrict__ gw,
          float* __restrict__ out)
{
    extern __shared__ float sm[];
    float* s_w  = sm;              // 189*64 = 12096 floats
    float* s_x0 = s_w + 12096;     // 18*18  = 324
    float* s_x1 = s_x0 + 324;      // 36*36  = 1296
    float* s_x2 = s_x1 + 1296;     // 72*72  = 5184   (total 75600 B)

    const int tid  = threadIdx.x;
    const int n    = blockIdx.z;
    const int i0   = blockIdx.y * 16;
    const int j0   = blockIdx.x * 16;
    const int lane = tid & 31;
    const int warp = tid >> 5;
    const int half = lane >> 4;                 // output half
    const int g    = warp * 16 + (lane & 15);   // position group 0..63
    const int j    = g & 15;                    // tile col
    const int r0   = (g >> 4) * 4;              // first of 4 tile rows

    // --- stage weights ---
    {
        const float4* wg = reinterpret_cast<const float4*>(gw);
        float4* ws = reinterpret_cast<float4*>(s_w);
        for (int idx = tid; idx < 3024; idx += NTHREADS) ws[idx] = wg[idx];
    }
    // --- stage x0 patch ---
    {
        const float* src = gx0 + n * 4096;
        for (int idx = tid; idx < 18 * 18; idx += NTHREADS) {
            int r = idx / 18, c = idx - r * 18;
            int gi = i0 - 1 + r, gj = j0 - 1 + c;
            float v = 0.0f;
            if ((unsigned)gi < 64u && (unsigned)gj < 64u) v = src[gi * 64 + gj];
            s_x0[idx] = v;
        }
    }
    // --- stage x1 patch ---
    {
        const float* src = gx1 + n * 16384;
        for (int idx = tid; idx < 36 * 36; idx += NTHREADS) {
            int r = idx / 36, c = idx - r * 36;
            int gi = 2 * i0 - 2 + r, gj = 2 * j0 - 2 + c;
            float v = 0.0f;
            if ((unsigned)gi < 128u && (unsigned)gj < 128u) v = src[gi * 128 + gj];
            s_x1[idx] = v;
        }
    }
    // --- stage x2 patch ---
    {
        const float* src = gx2 + n * 65536;
        for (int idx = tid; idx < 72 * 72; idx += NTHREADS) {
            int r = idx / 72, c = idx - r * 72;
            int gi = 4 * i0 - 4 + r, gj = 4 * j0 - 4 + c;
            float v = 0.0f;
            if ((unsigned)gi < 256u && (unsigned)gj < 256u) v = src[gi * 256 + gj];
            s_x2[idx] = v;
        }
    }
    __syncthreads();

    unsigned long long acc[64];
#pragma unroll
    for (int q = 0; q < 64; ++q) acc[q] = 0ull;

    const float* wk = s_w + half * 32;

    // layer 0: 3x3 taps; x0 row for pos p (p = r0+pp): (p+di)*18 + j + dj
#pragma unroll 1
    for (int di = 0; di < 3; ++di) {
        const float* xr = s_x0 + (r0 + di) * 18 + j;
#pragma unroll
        for (int dj = 0; dj < 3; ++dj) {
            tap4(acc, wk, xr[0 * 18 + dj], xr[1 * 18 + dj],
                          xr[2 * 18 + dj], xr[3 * 18 + dj]);
            wk += 64;
        }
    }
    // layer 1: 6x6 taps; row (2p+di)*36 + 2j + dj, pos stride = 2 rows
#pragma unroll 1
    for (int di = 0; di < 6; ++di) {
        const float* xr = s_x1 + (2 * r0 + di) * 36 + 2 * j;
#pragma unroll
        for (int dj = 0; dj < 6; ++dj) {
            tap4(acc, wk, xr[0 * 72 + dj], xr[1 * 72 + dj],
                          xr[2 * 72 + dj], xr[3 * 72 + dj]);
            wk += 64;
        }
    }
    // layer 2: 12x12 taps; row (4p+di)*72 + 4j + dj, pos stride = 4 rows
#pragma unroll 1
    for (int di = 0; di < 12; ++di) {
        const float* xr = s_x2 + (4 * r0 + di) * 72 + 4 * j;
#pragma unroll
        for (int dj = 0; dj < 12; ++dj) {
            tap4(acc, wk, xr[0 * 288 + dj], xr[1 * 288 + dj],
                          xr[2 * 288 + dj], xr[3 * 288 + dj]);
            wk += 64;
        }
    }

    // --- epilogue: relu -> softmax (half-split, shfl combine) -> scale -> store
#pragma unroll 1
    for (int pp = 0; pp < 4; ++pp) {
        float v[32];
        unsigned long long* a = acc + pp * 16;
#pragma unroll
        for (int q = 0; q < 16; ++q) {
            unsigned lo, hi;
            asm("mov.b64 {%0, %1}, %2;" : "=r"(lo), "=r"(hi) : "l"(a[q]));
            v[2 * q]     = fmaxf(__uint_as_float(lo), 0.0f);
            v[2 * q + 1] = fmaxf(__uint_as_float(hi), 0.0f);
        }
        float m = v[0];
#pragma unroll
        for (int o = 1; o < 32; ++o) m = fmaxf(m, v[o]);
        float s = 0.0f;
#pragma unroll
        for (int o = 0; o < 32; ++o) {
            v[o] = __expf(v[o] - m);
            s += v[o];
        }
        float pm = __shfl_xor_sync(0xffffffffu, m, 16);
        float ps = __shfl_xor_sync(0xffffffffu, s, 16);
        float M  = fmaxf(m, pm);
        float S  = s * __expf(m - M) + ps * __expf(pm - M);
        float corr = __expf(m - M);   // rescale own half to global max

        float xsel  = s_x0[(r0 + pp + 1) * 18 + (j + 1)];
        float scale = xsel * corr / S;

        int gi = i0 + r0 + pp, gj = j0 + j;
        float* base = out + ((size_t)n << 18)
                          + (size_t)(gi * 8 + half * 4) * 512 + gj * 8;
#pragma unroll
        for (int a2 = 0; a2 < 4; ++a2) {
            float4 t0 = make_float4(scale * v[a2 * 8 + 0], scale * v[a2 * 8 + 1],
                                    scale * v[a2 * 8 + 2], scale * v[a2 * 8 + 3]);
            float4 t1 = make_float4(scale * v[a2 * 8 + 4], scale * v[a2 * 8 + 5],
                                    scale * v[a2 * 8 + 6], scale * v[a2 * 8 + 7]);
            *reinterpret_cast<float4*>(base + (size_t)a2 * 512)     = t0;
            *reinterpret_cast<float4*>(base + (size_t)a2 * 512 + 4) = t1;
        }
    }
}

extern "C" void kernel_launch(void* const* d_in, const int* in_sizes, int n_in,
                              void* d_out, int out_size)
{
    const float* x0 = (const float*)d_in[0];
    const float* x1 = (const float*)d_in[1];
    const float* x2 = (const float*)d_in[2];
    const float* w  = (const float*)d_in[3];
    float* out = (float*)d_out;

    const int smem_bytes = 18900 * (int)sizeof(float);
    cudaFuncSetAttribute(sr_kernel, cudaFuncAttributeMaxDynamicSharedMemorySize,
                         smem_bytes);

    dim3 grid(4, 4, 64);
    sr_kernel<<<grid, NTHREADS, smem_bytes>>>(x0, x1, x2, w, out);
}